// round 7
// baseline (speedup 1.0000x reference)
#include <cuda_runtime.h>

#define NN 100000
#define NE 1600000
#define D  128
#define DOUT 40

#define SCAN_B 512
#define NSCANB ((NN + SCAN_B - 1) / SCAN_B)   // 196

#define TROWS 64
#define NTILES ((NN + TROWS - 1) / TROWS)     // 1563
#define XP_STRIDE 33                          // float2 units per k-row

typedef unsigned long long ull;

// Scratch (allocation-free rule: __device__ globals)
__device__ float g_bufA[(size_t)NN * D];    // t_s = (x@W1)*dinv  (gather source)
__device__ float g_bufB[(size_t)NN * D];    // layer-1 aggregated result
__device__ float g_bufU[(size_t)NN * DOUT]; // u_s = dinv*(h1@W2') (gather source)
__device__ float g_dinv[NN];
__device__ int   g_cnt[NN];
__device__ int   g_rowptr[NN];
__device__ int   g_woff[NN];
__device__ int   g_srcs[NE];
__device__ int   g_bsum[NSCANB];
__device__ int   g_boff[NSCANB];
__device__ float g_W2p[D * DOUT];           // W2 @ Wout
__device__ float g_c[DOUT];                 // b2 @ Wout + bout

__device__ __forceinline__ ull ffma2(ull a, ull b, ull c) {
    ull d;
    asm("fma.rn.f32x2 %0, %1, %2, %3;" : "=l"(d) : "l"(a), "l"(b), "l"(c));
    return d;
}
__device__ __forceinline__ ull pack2(float lo, float hi) {
    ull d;
    asm("mov.b64 %0, {%1, %2};" : "=l"(d) : "f"(lo), "f"(hi));
    return d;
}
__device__ __forceinline__ float2 unpack2(ull v) {
    float2 r;
    asm("mov.b64 {%0, %1}, %2;" : "=f"(r.x), "=f"(r.y) : "l"(v));
    return r;
}

// ---------------- CSR build ----------------
__global__ void k_zero() {
    int i = blockIdx.x * blockDim.x + threadIdx.x;
    if (i < NN) g_cnt[i] = 0;
}
__global__ void k_hist(const int* __restrict__ dst) {
    int i = blockIdx.x * blockDim.x + threadIdx.x;
    if (i < NE) atomicAdd(&g_cnt[dst[i]], 1);
}
__global__ __launch_bounds__(SCAN_B)
void k_scan1() {
    __shared__ int sh[SCAN_B];
    int i = blockIdx.x * SCAN_B + threadIdx.x;
    int v = (i < NN) ? g_cnt[i] : 0;
    sh[threadIdx.x] = v;
    __syncthreads();
    int acc = v;
#pragma unroll
    for (int off = 1; off < SCAN_B; off <<= 1) {
        int t = (threadIdx.x >= off) ? sh[threadIdx.x - off] : 0;
        __syncthreads();
        acc += t;
        sh[threadIdx.x] = acc;
        __syncthreads();
    }
    if (i < NN) g_rowptr[i] = acc - v;
    if (threadIdx.x == SCAN_B - 1) g_bsum[blockIdx.x] = acc;
}
__global__ __launch_bounds__(256)
void k_scan2() {
    __shared__ int sh[256];
    int t = threadIdx.x;
    int v = (t < NSCANB) ? g_bsum[t] : 0;
    sh[t] = v;
    __syncthreads();
    int acc = v;
#pragma unroll
    for (int off = 1; off < 256; off <<= 1) {
        int u = (t >= off) ? sh[t - off] : 0;
        __syncthreads();
        acc += u;
        sh[t] = acc;
        __syncthreads();
    }
    if (t < NSCANB) g_boff[t] = acc - v;
}
__global__ void k_finalize() {
    int i = blockIdx.x * blockDim.x + threadIdx.x;
    if (i < NN) {
        int p = g_rowptr[i] + g_boff[i / SCAN_B];
        g_rowptr[i] = p;
        g_woff[i]   = p;
        g_dinv[i]   = rsqrtf((float)(g_cnt[i] + 1));
    }
}
__global__ void k_scatter(const int* __restrict__ src, const int* __restrict__ dst) {
    int i = blockIdx.x * blockDim.x + threadIdx.x;
    if (i < NE) {
        int pos = atomicAdd(&g_woff[dst[i]], 1);
        g_srcs[pos] = src[i];
    }
}

// ---------------- weight folding ----------------
__global__ void k_fold(const float* __restrict__ W2, const float* __restrict__ Wout,
                       const float* __restrict__ b2, const float* __restrict__ bout)
{
    int t = blockIdx.x * blockDim.x + threadIdx.x;
    if (t < D * DOUT) {
        int k = t / DOUT, j = t % DOUT;
        float s = 0.f;
#pragma unroll 8
        for (int m = 0; m < D; m++)
            s = fmaf(W2[k * D + m], Wout[m * DOUT + j], s);
        g_W2p[t] = s;
    } else if (t < D * DOUT + DOUT) {
        int j = t - D * DOUT;
        float s = bout[j];
#pragma unroll 8
        for (int m = 0; m < D; m++)
            s = fmaf(b2[m], Wout[m * DOUT + j], s);
        g_c[j] = s;
    }
}

// ---------------- GEMM1: row-pair f32x2, CTA-staged transposed X ----------------
// t = x @ W1; write t*dinv -> bufA. Persistent blocks over 64-row tiles.
__global__ __launch_bounds__(256, 2)
void k_gemm(const float* __restrict__ X, const float* __restrict__ W)
{
    extern __shared__ float sh[];
    float* Ws = sh;                               // 128*128 floats
    ull*   Xp = (ull*)(sh + D * D);               // [128][XP_STRIDE] float2 (as ull)

    const int tid = threadIdx.x;
    const int lane = tid & 31, warp = tid >> 5;
    const int rpb = warp * 4;                     // rowpairs 4w..4w+3

    for (int i = tid; i < D * D / 4; i += 256)
        ((float4*)Ws)[i] = ((const float4*)W)[i];

    for (int tile = blockIdx.x; tile < NTILES; tile += gridDim.x) {
        const int rbase = tile * TROWS;

        // stage 64 rows transposed into pair layout (swizzled)
        float* Xf = (float*)Xp;
        for (int idx = tid; idx < TROWS * 32; idx += 256) {
            int row = idx >> 5, c4 = idx & 31;
            int grow = rbase + row;
            float4 v = make_float4(0.f, 0.f, 0.f, 0.f);
            if (grow < NN) v = ((const float4*)(X + (size_t)grow * D))[c4];
            int rp = row >> 1, lo = row & 1;
            int sidx = (rp + c4) & 31;
            int k0 = 4 * c4;
            Xf[((k0 + 0) * XP_STRIDE + sidx) * 2 + lo] = v.x;
            Xf[((k0 + 1) * XP_STRIDE + sidx) * 2 + lo] = v.y;
            Xf[((k0 + 2) * XP_STRIDE + sidx) * 2 + lo] = v.z;
            Xf[((k0 + 3) * XP_STRIDE + sidx) * 2 + lo] = v.w;
        }
        __syncthreads();

        ull acc[4][4];
#pragma unroll
        for (int i = 0; i < 4; i++)
#pragma unroll
            for (int c = 0; c < 4; c++) acc[i][c] = 0ull;

#pragma unroll 4
        for (int k = 0; k < D; k++) {
            float4 w = *(const float4*)(Ws + k * D + 4 * lane);
            ull w0 = pack2(w.x, w.x);
            ull w1 = pack2(w.y, w.y);
            ull w2 = pack2(w.z, w.z);
            ull w3 = pack2(w.w, w.w);
            int sw = k >> 2;
            ull x0 = Xp[k * XP_STRIDE + ((rpb + 0 + sw) & 31)];
            ull x1 = Xp[k * XP_STRIDE + ((rpb + 1 + sw) & 31)];
            ull x2 = Xp[k * XP_STRIDE + ((rpb + 2 + sw) & 31)];
            ull x3 = Xp[k * XP_STRIDE + ((rpb + 3 + sw) & 31)];
            acc[0][0] = ffma2(x0, w0, acc[0][0]);
            acc[0][1] = ffma2(x0, w1, acc[0][1]);
            acc[0][2] = ffma2(x0, w2, acc[0][2]);
            acc[0][3] = ffma2(x0, w3, acc[0][3]);
            acc[1][0] = ffma2(x1, w0, acc[1][0]);
            acc[1][1] = ffma2(x1, w1, acc[1][1]);
            acc[1][2] = ffma2(x1, w2, acc[1][2]);
            acc[1][3] = ffma2(x1, w3, acc[1][3]);
            acc[2][0] = ffma2(x2, w0, acc[2][0]);
            acc[2][1] = ffma2(x2, w1, acc[2][1]);
            acc[2][2] = ffma2(x2, w2, acc[2][2]);
            acc[2][3] = ffma2(x2, w3, acc[2][3]);
            acc[3][0] = ffma2(x3, w0, acc[3][0]);
            acc[3][1] = ffma2(x3, w1, acc[3][1]);
            acc[3][2] = ffma2(x3, w2, acc[3][2]);
            acc[3][3] = ffma2(x3, w3, acc[3][3]);
        }

#pragma unroll
        for (int i = 0; i < 4; i++) {
            int r0 = rbase + 2 * (rpb + i);
            if (r0 < NN) {                        // NN even -> pair never straddles
                int r1 = r0 + 1;
                float d0 = g_dinv[r0], d1 = g_dinv[r1];
                float2 p0 = unpack2(acc[i][0]);
                float2 p1 = unpack2(acc[i][1]);
                float2 p2 = unpack2(acc[i][2]);
                float2 p3 = unpack2(acc[i][3]);
                float4 o0 = make_float4(p0.x * d0, p1.x * d0, p2.x * d0, p3.x * d0);
                float4 o1 = make_float4(p0.y * d1, p1.y * d1, p2.y * d1, p3.y * d1);
                *(float4*)(g_bufA + (size_t)r0 * D + 4 * lane) = o0;
                *(float4*)(g_bufA + (size_t)r1 * D + 4 * lane) = o1;
            }
        }
        __syncthreads();
    }
}

// ---------------- CSR gather (128-dim): warp per node ----------------
__global__ __launch_bounds__(256)
void k_gather()
{
    const int v = (blockIdx.x * blockDim.x + threadIdx.x) >> 5;
    if (v >= NN) return;
    const int lane = threadIdx.x & 31;
    const int start = g_rowptr[v];
    const int deg   = g_cnt[v];

    float4 acc = ((const float4*)(g_bufA + (size_t)v * D))[lane];

    int j = 0;
    for (; j + 4 <= deg; j += 4) {
        int s0 = __ldg(g_srcs + start + j + 0);
        int s1 = __ldg(g_srcs + start + j + 1);
        int s2 = __ldg(g_srcs + start + j + 2);
        int s3 = __ldg(g_srcs + start + j + 3);
        float4 v0 = ((const float4*)(g_bufA + (size_t)s0 * D))[lane];
        float4 v1 = ((const float4*)(g_bufA + (size_t)s1 * D))[lane];
        float4 v2 = ((const float4*)(g_bufA + (size_t)s2 * D))[lane];
        float4 v3 = ((const float4*)(g_bufA + (size_t)s3 * D))[lane];
        acc.x += v0.x + v1.x + v2.x + v3.x;
        acc.y += v0.y + v1.y + v2.y + v3.y;
        acc.z += v0.z + v1.z + v2.z + v3.z;
        acc.w += v0.w + v1.w + v2.w + v3.w;
    }
    for (; j < deg; j++) {
        int s = __ldg(g_srcs + start + j);
        float4 u = ((const float4*)(g_bufA + (size_t)s * D))[lane];
        acc.x += u.x; acc.y += u.y; acc.z += u.z; acc.w += u.w;
    }
    ((float4*)(g_bufB + (size_t)v * D))[lane] = acc;
}

// ---------------- small GEMM: u = [relu(dinv*agg1+b1) @ W2'] * dinv -> bufU ----------------
// Row-pair f32x2, CTA-staged activated X. W2' padded to 128x64 in smem.
__global__ __launch_bounds__(256, 3)
void k_small(const float* __restrict__ b1)
{
    extern __shared__ float sh[];
    float* Ws = sh;                               // 128*64 (cols 40..63 zero)
    ull*   Xp = (ull*)(sh + D * 64);

    const int tid = threadIdx.x;
    const int lane = tid & 31, warp = tid >> 5;
    const int rpb = warp * 4;

    for (int i = tid; i < D * 64; i += 256) {
        int k = i >> 6, j = i & 63;
        Ws[i] = (j < DOUT) ? g_W2p[k * DOUT + j] : 0.f;
    }

    for (int tile = blockIdx.x; tile < NTILES; tile += gridDim.x) {
        const int rbase = tile * TROWS;

        float* Xf = (float*)Xp;
        for (int idx = tid; idx < TROWS * 32; idx += 256) {
            int row = idx >> 5, c4 = idx & 31;
            int grow = rbase + row;
            float4 v = make_float4(0.f, 0.f, 0.f, 0.f);
            if (grow < NN) {
                float di = g_dinv[grow];
                float4 a = ((const float4*)(g_bufB + (size_t)grow * D))[c4];
                float4 b = __ldg((const float4*)b1 + c4);
                v.x = fmaxf(fmaf(di, a.x, b.x), 0.f);
                v.y = fmaxf(fmaf(di, a.y, b.y), 0.f);
                v.z = fmaxf(fmaf(di, a.z, b.z), 0.f);
                v.w = fmaxf(fmaf(di, a.w, b.w), 0.f);
            }
            int rp = row >> 1, lo = row & 1;
            int sidx = (rp + c4) & 31;
            int k0 = 4 * c4;
            Xf[((k0 + 0) * XP_STRIDE + sidx) * 2 + lo] = v.x;
            Xf[((k0 + 1) * XP_STRIDE + sidx) * 2 + lo] = v.y;
            Xf[((k0 + 2) * XP_STRIDE + sidx) * 2 + lo] = v.z;
            Xf[((k0 + 3) * XP_STRIDE + sidx) * 2 + lo] = v.w;
        }
        __syncthreads();

        ull acc[4][2];
#pragma unroll
        for (int i = 0; i < 4; i++) { acc[i][0] = 0ull; acc[i][1] = 0ull; }

#pragma unroll 4
        for (int k = 0; k < D; k++) {
            float2 w = *(const float2*)(Ws + k * 64 + 2 * lane);
            ull w0 = pack2(w.x, w.x);
            ull w1 = pack2(w.y, w.y);
            int sw = k >> 2;
            ull x0 = Xp[k * XP_STRIDE + ((rpb + 0 + sw) & 31)];
            ull x1 = Xp[k * XP_STRIDE + ((rpb + 1 + sw) & 31)];
            ull x2 = Xp[k * XP_STRIDE + ((rpb + 2 + sw) & 31)];
            ull x3 = Xp[k * XP_STRIDE + ((rpb + 3 + sw) & 31)];
            acc[0][0] = ffma2(x0, w0, acc[0][0]);
            acc[0][1] = ffma2(x0, w1, acc[0][1]);
            acc[1][0] = ffma2(x1, w0, acc[1][0]);
            acc[1][1] = ffma2(x1, w1, acc[1][1]);
            acc[2][0] = ffma2(x2, w0, acc[2][0]);
            acc[2][1] = ffma2(x2, w1, acc[2][1]);
            acc[3][0] = ffma2(x3, w0, acc[3][0]);
            acc[3][1] = ffma2(x3, w1, acc[3][1]);
        }

        if (lane < DOUT / 2) {
#pragma unroll
            for (int i = 0; i < 4; i++) {
                int r0 = rbase + 2 * (rpb + i);
                if (r0 < NN) {
                    int r1 = r0 + 1;
                    float d0 = g_dinv[r0], d1 = g_dinv[r1];
                    float2 p0 = unpack2(acc[i][0]);
                    float2 p1 = unpack2(acc[i][1]);
                    float2 o0 = make_float2(p0.x * d0, p1.x * d0);
                    float2 o1 = make_float2(p0.y * d1, p1.y * d1);
                    *(float2*)(g_bufU + (size_t)r0 * DOUT + 2 * lane) = o0;
                    *(float2*)(g_bufU + (size_t)r1 * DOUT + 2 * lane) = o1;
                }
            }
        }
        __syncthreads();
    }
}

// ---------------- CSR gather (40-dim) + final epilogue ----------------
__global__ __launch_bounds__(256)
void k_gather2(float* __restrict__ out)
{
    const int v = (blockIdx.x * blockDim.x + threadIdx.x) >> 5;
    if (v >= NN) return;
    const int lane = threadIdx.x & 31;
    if (lane >= DOUT / 2) return;
    const int start = g_rowptr[v];
    const int deg   = g_cnt[v];
    const float di  = g_dinv[v];

    float2 acc = *(const float2*)(g_bufU + (size_t)v * DOUT + 2 * lane);

    int j = 0;
    for (; j + 4 <= deg; j += 4) {
        int s0 = __ldg(g_srcs + start + j + 0);
        int s1 = __ldg(g_srcs + start + j + 1);
        int s2 = __ldg(g_srcs + start + j + 2);
        int s3 = __ldg(g_srcs + start + j + 3);
        float2 v0 = *(const float2*)(g_bufU + (size_t)s0 * DOUT + 2 * lane);
        float2 v1 = *(const float2*)(g_bufU + (size_t)s1 * DOUT + 2 * lane);
        float2 v2 = *(const float2*)(g_bufU + (size_t)s2 * DOUT + 2 * lane);
        float2 v3 = *(const float2*)(g_bufU + (size_t)s3 * DOUT + 2 * lane);
        acc.x += v0.x + v1.x + v2.x + v3.x;
        acc.y += v0.y + v1.y + v2.y + v3.y;
    }
    for (; j < deg; j++) {
        int s = __ldg(g_srcs + start + j);
        float2 u = *(const float2*)(g_bufU + (size_t)s * DOUT + 2 * lane);
        acc.x += u.x; acc.y += u.y;
    }
    float2 c = *(const float2*)(g_c + 2 * lane);
    float2 o = make_float2(fmaf(di, acc.x, c.x), fmaf(di, acc.y, c.y));
    *(float2*)(out + (size_t)v * DOUT + 2 * lane) = o;
}

extern "C" void kernel_launch(void* const* d_in, const int* in_sizes, int n_in,
                              void* d_out, int out_size)
{
    const float* x    = (const float*)d_in[0];
    const int*   ei   = (const int*)  d_in[1];
    const float* W1   = (const float*)d_in[2];
    const float* b1   = (const float*)d_in[3];
    const float* W2   = (const float*)d_in[4];
    const float* b2   = (const float*)d_in[5];
    const float* Wout = (const float*)d_in[6];
    const float* bout = (const float*)d_in[7];
    const int* src = ei;
    const int* dst = ei + NE;
    float* out = (float*)d_out;

    const int SMEM_GEMM  = (D * D) * 4 + D * XP_STRIDE * 8;   // 64KB + 33KB
    const int SMEM_SMALL = (D * 64) * 4 + D * XP_STRIDE * 8;  // 32KB + 33KB

    cudaFuncSetAttribute(k_gemm,  cudaFuncAttributeMaxDynamicSharedMemorySize, SMEM_GEMM);
    cudaFuncSetAttribute(k_small, cudaFuncAttributeMaxDynamicSharedMemorySize, SMEM_SMALL);

    const int GATHER_GRID = (NN * 32 + 255) / 256;
    const int GEMM_GRID   = 304;   // 2 CTAs/SM persistent
    const int SMALL_GRID  = 456;   // 3 CTAs/SM persistent

    // ---- CSR build + weight folding ----
    k_zero<<<(NN + 255) / 256, 256>>>();
    k_hist<<<(NE + 255) / 256, 256>>>(dst);
    k_fold<<<(D * DOUT + DOUT + 255) / 256, 256>>>(W2, Wout, b2, bout);
    k_scan1<<<NSCANB, SCAN_B>>>();
    k_scan2<<<1, 256>>>();
    k_finalize<<<(NN + 255) / 256, 256>>>();
    k_scatter<<<(NE + 255) / 256, 256>>>(src, dst);

    // ---- layer 1 ----
    k_gemm<<<GEMM_GRID, 256, SMEM_GEMM>>>(x, W1);
    k_gather<<<GATHER_GRID, 256>>>();

    // ---- layer 2 folded with output layer ----
    k_small<<<SMALL_GRID, 256, SMEM_SMALL>>>(b1);
    k_gather2<<<GATHER_GRID, 256>>>(out);
}

// round 12
// speedup vs baseline: 1.3215x; 1.3215x over previous
#include <cuda_runtime.h>

#define NN 100000
#define NE 1600000
#define D  128
#define DOUT 40
#define ROWS 8
#define NGROUP (NN / ROWS)

#define SCAN_B 512
#define NSCANB ((NN + SCAN_B - 1) / SCAN_B)   // 196

typedef unsigned long long ull;

// Scratch (allocation-free rule: __device__ globals)
__device__ float g_bufA[(size_t)NN * D];    // t_s = (x@W1)*dinv  (gather source)
__device__ float g_bufU[(size_t)NN * DOUT]; // u_s = dinv*(h1@W2') (gather source)
__device__ float g_dinv[NN];
__device__ int   g_cnt[NN];
__device__ int   g_rowptr[NN];
__device__ int   g_woff[NN];
__device__ int   g_srcs[NE];
__device__ int   g_bsum[NSCANB];
__device__ int   g_boff[NSCANB];
__device__ float g_W2p[D * DOUT];           // W2 @ Wout
__device__ float g_c[DOUT];                 // b2 @ Wout + bout

__device__ __forceinline__ ull ffma2(ull a, ull b, ull c) {
    ull d;
    asm("fma.rn.f32x2 %0, %1, %2, %3;" : "=l"(d) : "l"(a), "l"(b), "l"(c));
    return d;
}
__device__ __forceinline__ ull pack2(float lo, float hi) {
    ull d;
    asm("mov.b64 %0, {%1, %2};" : "=l"(d) : "f"(lo), "f"(hi));
    return d;
}
__device__ __forceinline__ float2 unpack2(ull v) {
    float2 r;
    asm("mov.b64 {%0, %1}, %2;" : "=f"(r.x), "=f"(r.y) : "l"(v));
    return r;
}

// ---------------- CSR build ----------------
__global__ void k_zero() {
    int i = blockIdx.x * blockDim.x + threadIdx.x;
    if (i < NN) g_cnt[i] = 0;
}
__global__ void k_hist(const int* __restrict__ dst) {
    int i = blockIdx.x * blockDim.x + threadIdx.x;
    if (i < NE) atomicAdd(&g_cnt[dst[i]], 1);
}
__global__ __launch_bounds__(SCAN_B)
void k_scan1() {
    __shared__ int sh[SCAN_B];
    int i = blockIdx.x * SCAN_B + threadIdx.x;
    int v = (i < NN) ? g_cnt[i] : 0;
    sh[threadIdx.x] = v;
    __syncthreads();
    int acc = v;
#pragma unroll
    for (int off = 1; off < SCAN_B; off <<= 1) {
        int t = (threadIdx.x >= off) ? sh[threadIdx.x - off] : 0;
        __syncthreads();
        acc += t;
        sh[threadIdx.x] = acc;
        __syncthreads();
    }
    if (i < NN) g_rowptr[i] = acc - v;
    if (threadIdx.x == SCAN_B - 1) g_bsum[blockIdx.x] = acc;
}
__global__ __launch_bounds__(256)
void k_scan2() {
    __shared__ int sh[256];
    int t = threadIdx.x;
    int v = (t < NSCANB) ? g_bsum[t] : 0;
    sh[t] = v;
    __syncthreads();
    int acc = v;
#pragma unroll
    for (int off = 1; off < 256; off <<= 1) {
        int u = (t >= off) ? sh[t - off] : 0;
        __syncthreads();
        acc += u;
        sh[t] = acc;
        __syncthreads();
    }
    if (t < NSCANB) g_boff[t] = acc - v;   // exclusive
}
__global__ void k_finalize() {
    int i = blockIdx.x * blockDim.x + threadIdx.x;
    if (i < NN) {
        int p = g_rowptr[i] + g_boff[i / SCAN_B];
        g_rowptr[i] = p;
        g_woff[i]   = p;
        g_dinv[i]   = rsqrtf((float)(g_cnt[i] + 1));
    }
}
__global__ void k_scatter(const int* __restrict__ src, const int* __restrict__ dst) {
    int i = blockIdx.x * blockDim.x + threadIdx.x;
    if (i < NE) {
        int pos = atomicAdd(&g_woff[dst[i]], 1);
        g_srcs[pos] = src[i];
    }
}

// ---------------- weight folding: W2' = W2 @ Wout ; c = b2 @ Wout + bout ----------------
__global__ void k_fold(const float* __restrict__ W2, const float* __restrict__ Wout,
                       const float* __restrict__ b2, const float* __restrict__ bout)
{
    int t = blockIdx.x * blockDim.x + threadIdx.x;
    if (t < D * DOUT) {
        int k = t / DOUT, j = t % DOUT;
        float s = 0.f;
#pragma unroll 8
        for (int m = 0; m < D; m++)
            s = fmaf(W2[k * D + m], Wout[m * DOUT + j], s);
        g_W2p[t] = s;
    } else if (t < D * DOUT + DOUT) {
        int j = t - D * DOUT;
        float s = bout[j];
#pragma unroll 8
        for (int m = 0; m < D; m++)
            s = fmaf(b2[m], Wout[m * DOUT + j], s);
        g_c[j] = s;
    }
}

// ---------------- GEMM1 (8 rows per warp, FFMA2, W in smem) ----------------
// t = x @ W1; write t*dinv -> bufA
__global__ __launch_bounds__(256)
void k_gemm(const float* __restrict__ X, const float* __restrict__ W)
{
    extern __shared__ float Ws[];          // D*D floats
    const int tid = threadIdx.x;
    for (int i = tid; i < D * D / 4; i += blockDim.x)
        ((float4*)Ws)[i] = ((const float4*)W)[i];
    __syncthreads();

    const int lane = tid & 31, warp = tid >> 5;
    const int NW = blockDim.x >> 5;

    for (int g = blockIdx.x * NW + warp; g < NGROUP; g += gridDim.x * NW) {
        const int row0 = g * ROWS;
        float xr[ROWS][4];
        float di[ROWS];
#pragma unroll
        for (int r = 0; r < ROWS; r++) {
            const int row = row0 + r;
            di[r] = g_dinv[row];
            float4 v = ((const float4*)(X + (size_t)row * D))[lane];
            xr[r][0] = v.x; xr[r][1] = v.y; xr[r][2] = v.z; xr[r][3] = v.w;
        }

        ull acc0[ROWS], acc1[ROWS];
#pragma unroll
        for (int r = 0; r < ROWS; r++) { acc0[r] = 0ull; acc1[r] = 0ull; }

#pragma unroll 4
        for (int k = 0; k < D; k++) {
            ulonglong2 w = ((const ulonglong2*)Ws)[k * 32 + lane];
#pragma unroll
            for (int r = 0; r < ROWS; r++) {
                float xv = __shfl_sync(0xffffffffu, xr[r][k & 3], k >> 2);
                ull xvv = pack2(xv, xv);
                acc0[r] = ffma2(xvv, w.x, acc0[r]);
                acc1[r] = ffma2(xvv, w.y, acc1[r]);
            }
        }

#pragma unroll
        for (int r = 0; r < ROWS; r++) {
            const int row = row0 + r;
            float2 lo = unpack2(acc0[r]);
            float2 hi = unpack2(acc1[r]);
            float4 o = make_float4(lo.x * di[r], lo.y * di[r],
                                   hi.x * di[r], hi.y * di[r]);
            ((float4*)(g_bufA + (size_t)row * D))[lane] = o;
        }
    }
}

// ---------------- fused gather(128-dim) + small GEMM ----------------
// per row: agg = bufA[row] + sum_{s in N(row)} bufA[s]
//          h   = relu(dinv*agg + b1)
//          u   = (h @ W2') * dinv -> bufU
__global__ __launch_bounds__(256)
void k_small(const float* __restrict__ b1)
{
    extern __shared__ float Ws[];          // D*DOUT floats
    const int tid = threadIdx.x;
    for (int i = tid; i < D * DOUT; i += blockDim.x)
        Ws[i] = g_W2p[i];
    __syncthreads();

    const int lane = tid & 31, warp = tid >> 5;
    const int NW = blockDim.x >> 5;
    const bool act = (lane < DOUT / 2);

    float4 b1r = ((const float4*)b1)[lane];

    for (int g = blockIdx.x * NW + warp; g < NGROUP; g += gridDim.x * NW) {
        const int row0 = g * ROWS;
        float xr[ROWS][4];
        float di[ROWS];
#pragma unroll
        for (int r = 0; r < ROWS; r++) {
            const int row = row0 + r;
            di[r] = g_dinv[row];
            const int start = g_rowptr[row];
            const int deg   = g_cnt[row];

            float4 a = ((const float4*)(g_bufA + (size_t)row * D))[lane]; // self

            int j = 0;
            for (; j + 4 <= deg; j += 4) {
                int s0 = __ldg(g_srcs + start + j + 0);
                int s1 = __ldg(g_srcs + start + j + 1);
                int s2 = __ldg(g_srcs + start + j + 2);
                int s3 = __ldg(g_srcs + start + j + 3);
                float4 v0 = ((const float4*)(g_bufA + (size_t)s0 * D))[lane];
                float4 v1 = ((const float4*)(g_bufA + (size_t)s1 * D))[lane];
                float4 v2 = ((const float4*)(g_bufA + (size_t)s2 * D))[lane];
                float4 v3 = ((const float4*)(g_bufA + (size_t)s3 * D))[lane];
                a.x += v0.x + v1.x + v2.x + v3.x;
                a.y += v0.y + v1.y + v2.y + v3.y;
                a.z += v0.z + v1.z + v2.z + v3.z;
                a.w += v0.w + v1.w + v2.w + v3.w;
            }
            for (; j < deg; j++) {
                int s = __ldg(g_srcs + start + j);
                float4 u = ((const float4*)(g_bufA + (size_t)s * D))[lane];
                a.x += u.x; a.y += u.y; a.z += u.z; a.w += u.w;
            }

            xr[r][0] = fmaxf(fmaf(di[r], a.x, b1r.x), 0.f);
            xr[r][1] = fmaxf(fmaf(di[r], a.y, b1r.y), 0.f);
            xr[r][2] = fmaxf(fmaf(di[r], a.z, b1r.z), 0.f);
            xr[r][3] = fmaxf(fmaf(di[r], a.w, b1r.w), 0.f);
        }

        ull acc[ROWS];
#pragma unroll
        for (int r = 0; r < ROWS; r++) acc[r] = 0ull;

#pragma unroll 4
        for (int k = 0; k < D; k++) {
            ull w = 0ull;
            if (act) w = *(const ull*)(Ws + k * DOUT + 2 * lane);
#pragma unroll
            for (int r = 0; r < ROWS; r++) {
                float xv = __shfl_sync(0xffffffffu, xr[r][k & 3], k >> 2);
                ull xvv = pack2(xv, xv);
                acc[r] = ffma2(xvv, w, acc[r]);
            }
        }

        if (act) {
#pragma unroll
            for (int r = 0; r < ROWS; r++) {
                float2 v = unpack2(acc[r]);
                float2 o = make_float2(v.x * di[r], v.y * di[r]);
                *(float2*)(g_bufU + (size_t)(row0 + r) * DOUT + 2 * lane) = o;
            }
        }
    }
}

// ---------------- CSR gather (40-dim) + final epilogue: out = dinv*acc + c ----------------
__global__ __launch_bounds__(256)
void k_gather2(float* __restrict__ out)
{
    const int v = (blockIdx.x * blockDim.x + threadIdx.x) >> 5;
    if (v >= NN) return;
    const int lane = threadIdx.x & 31;
    if (lane >= DOUT / 2) return;
    const int start = g_rowptr[v];
    const int deg   = g_cnt[v];
    const float di  = g_dinv[v];

    float2 acc = *(const float2*)(g_bufU + (size_t)v * DOUT + 2 * lane);  // self

    int j = 0;
    for (; j + 4 <= deg; j += 4) {
        int s0 = __ldg(g_srcs + start + j + 0);
        int s1 = __ldg(g_srcs + start + j + 1);
        int s2 = __ldg(g_srcs + start + j + 2);
        int s3 = __ldg(g_srcs + start + j + 3);
        float2 v0 = *(const float2*)(g_bufU + (size_t)s0 * DOUT + 2 * lane);
        float2 v1 = *(const float2*)(g_bufU + (size_t)s1 * DOUT + 2 * lane);
        float2 v2 = *(const float2*)(g_bufU + (size_t)s2 * DOUT + 2 * lane);
        float2 v3 = *(const float2*)(g_bufU + (size_t)s3 * DOUT + 2 * lane);
        acc.x += v0.x + v1.x + v2.x + v3.x;
        acc.y += v0.y + v1.y + v2.y + v3.y;
    }
    for (; j < deg; j++) {
        int s = __ldg(g_srcs + start + j);
        float2 u = *(const float2*)(g_bufU + (size_t)s * DOUT + 2 * lane);
        acc.x += u.x; acc.y += u.y;
    }
    float2 c = *(const float2*)(g_c + 2 * lane);
    float2 o = make_float2(fmaf(di, acc.x, c.x), fmaf(di, acc.y, c.y));
    *(float2*)(out + (size_t)v * DOUT + 2 * lane) = o;
}

extern "C" void kernel_launch(void* const* d_in, const int* in_sizes, int n_in,
                              void* d_out, int out_size)
{
    const float* x    = (const float*)d_in[0];
    const int*   ei   = (const int*)  d_in[1];
    const float* W1   = (const float*)d_in[2];
    const float* b1   = (const float*)d_in[3];
    const float* W2   = (const float*)d_in[4];
    const float* b2   = (const float*)d_in[5];
    const float* Wout = (const float*)d_in[6];
    const float* bout = (const float*)d_in[7];
    const int* src = ei;
    const int* dst = ei + NE;
    float* out = (float*)d_out;

    const int SMEM_GEMM  = D * D * 4;       // 64 KB
    const int SMEM_SMALL = D * DOUT * 4;    // 20 KB

    cudaFuncSetAttribute(k_gemm, cudaFuncAttributeMaxDynamicSharedMemorySize, SMEM_GEMM);

    const int GEMM_GRID   = (NGROUP + 7) / 8;
    const int GATHER_GRID = (NN * 32 + 255) / 256;

    // ---- CSR build + weight folding ----
    k_zero<<<(NN + 255) / 256, 256>>>();
    k_hist<<<(NE + 255) / 256, 256>>>(dst);
    k_fold<<<(D * DOUT + DOUT + 255) / 256, 256>>>(W2, Wout, b2, bout);
    k_scan1<<<NSCANB, SCAN_B>>>();
    k_scan2<<<1, 256>>>();
    k_finalize<<<(NN + 255) / 256, 256>>>();
    k_scatter<<<(NE + 255) / 256, 256>>>(src, dst);

    // ---- layer 1 ----
    k_gemm<<<GEMM_GRID, 256, SMEM_GEMM>>>(x, W1);

    // ---- layer 2 folded with output layer; gather1 fused in ----
    k_small<<<GEMM_GRID, 256, SMEM_SMALL>>>(b1);
    k_gather2<<<GATHER_GRID, 256>>>(out);
}

// round 13
// speedup vs baseline: 1.3973x; 1.0573x over previous
#include <cuda_runtime.h>
#include <cuda_fp16.h>

#define NN 100000
#define NE 1600000
#define D  128
#define DOUT 40
#define ROWS 8
#define NGROUP (NN / ROWS)

#define SCAN_B 512
#define NSCANB ((NN + SCAN_B - 1) / SCAN_B)   // 196

typedef unsigned long long ull;

// Scratch (allocation-free rule: __device__ globals)
__device__ __align__(16) __half g_bufAh[(size_t)NN * D];    // fp16 t_s (gather src)
__device__ float  g_bufB[(size_t)NN * D];                   // fp32 aggregated layer-1
__device__ __align__(16) __half g_bufUh[(size_t)NN * DOUT]; // fp16 u_s (gather src)
__device__ float g_dinv[NN];
__device__ int   g_cnt[NN];
__device__ int   g_rowptr[NN];
__device__ int   g_woff[NN];
__device__ int   g_srcs[NE];
__device__ int   g_bsum[NSCANB];
__device__ int   g_boff[NSCANB];
__device__ float g_W2p[D * DOUT];           // W2 @ Wout
__device__ float g_c[DOUT];                 // b2 @ Wout + bout

__device__ __forceinline__ ull ffma2(ull a, ull b, ull c) {
    ull d;
    asm("fma.rn.f32x2 %0, %1, %2, %3;" : "=l"(d) : "l"(a), "l"(b), "l"(c));
    return d;
}
__device__ __forceinline__ ull pack2(float lo, float hi) {
    ull d;
    asm("mov.b64 %0, {%1, %2};" : "=l"(d) : "f"(lo), "f"(hi));
    return d;
}
__device__ __forceinline__ float2 unpack2(ull v) {
    float2 r;
    asm("mov.b64 {%0, %1}, %2;" : "=f"(r.x), "=f"(r.y) : "l"(v));
    return r;
}
// load 4 halves (8B) -> float4
__device__ __forceinline__ float4 ldh4(const __half* p) {
    uint2 raw = *(const uint2*)p;
    __half2 h0 = *(__half2*)&raw.x;
    __half2 h1 = *(__half2*)&raw.y;
    float2 f0 = __half22float2(h0);
    float2 f1 = __half22float2(h1);
    return make_float4(f0.x, f0.y, f1.x, f1.y);
}

// ---------------- CSR build ----------------
__global__ void k_zero() {
    int i = blockIdx.x * blockDim.x + threadIdx.x;
    if (i < NN) g_cnt[i] = 0;
}
__global__ void k_hist(const int* __restrict__ dst) {
    int i = blockIdx.x * blockDim.x + threadIdx.x;
    if (i < NE) atomicAdd(&g_cnt[dst[i]], 1);
}
__global__ __launch_bounds__(SCAN_B)
void k_scan1() {
    __shared__ int sh[SCAN_B];
    int i = blockIdx.x * SCAN_B + threadIdx.x;
    int v = (i < NN) ? g_cnt[i] : 0;
    sh[threadIdx.x] = v;
    __syncthreads();
    int acc = v;
#pragma unroll
    for (int off = 1; off < SCAN_B; off <<= 1) {
        int t = (threadIdx.x >= off) ? sh[threadIdx.x - off] : 0;
        __syncthreads();
        acc += t;
        sh[threadIdx.x] = acc;
        __syncthreads();
    }
    if (i < NN) g_rowptr[i] = acc - v;
    if (threadIdx.x == SCAN_B - 1) g_bsum[blockIdx.x] = acc;
}
__global__ __launch_bounds__(256)
void k_scan2() {
    __shared__ int sh[256];
    int t = threadIdx.x;
    int v = (t < NSCANB) ? g_bsum[t] : 0;
    sh[t] = v;
    __syncthreads();
    int acc = v;
#pragma unroll
    for (int off = 1; off < 256; off <<= 1) {
        int u = (t >= off) ? sh[t - off] : 0;
        __syncthreads();
        acc += u;
        sh[t] = acc;
        __syncthreads();
    }
    if (t < NSCANB) g_boff[t] = acc - v;   // exclusive
}
__global__ void k_finalize() {
    int i = blockIdx.x * blockDim.x + threadIdx.x;
    if (i < NN) {
        int p = g_rowptr[i] + g_boff[i / SCAN_B];
        g_rowptr[i] = p;
        g_woff[i]   = p;
        g_dinv[i]   = rsqrtf((float)(g_cnt[i] + 1));
    }
}
__global__ void k_scatter(const int* __restrict__ src, const int* __restrict__ dst) {
    int i = blockIdx.x * blockDim.x + threadIdx.x;
    if (i < NE) {
        int pos = atomicAdd(&g_woff[dst[i]], 1);
        g_srcs[pos] = src[i];
    }
}

// ---------------- weight folding: W2' = W2 @ Wout ; c = b2 @ Wout + bout ----------------
__global__ void k_fold(const float* __restrict__ W2, const float* __restrict__ Wout,
                       const float* __restrict__ b2, const float* __restrict__ bout)
{
    int t = blockIdx.x * blockDim.x + threadIdx.x;
    if (t < D * DOUT) {
        int k = t / DOUT, j = t % DOUT;
        float s = 0.f;
#pragma unroll 8
        for (int m = 0; m < D; m++)
            s = fmaf(W2[k * D + m], Wout[m * DOUT + j], s);
        g_W2p[t] = s;
    } else if (t < D * DOUT + DOUT) {
        int j = t - D * DOUT;
        float s = bout[j];
#pragma unroll 8
        for (int m = 0; m < D; m++)
            s = fmaf(b2[m], Wout[m * DOUT + j], s);
        g_c[j] = s;
    }
}

// ---------------- GEMM1 (8 rows per warp, FFMA2, W in smem) ----------------
// t = x @ W1; write fp16(t*dinv) -> bufAh
__global__ __launch_bounds__(256)
void k_gemm(const float* __restrict__ X, const float* __restrict__ W)
{
    extern __shared__ float Ws[];          // D*D floats
    const int tid = threadIdx.x;
    for (int i = tid; i < D * D / 4; i += blockDim.x)
        ((float4*)Ws)[i] = ((const float4*)W)[i];
    __syncthreads();

    const int lane = tid & 31, warp = tid >> 5;
    const int NW = blockDim.x >> 5;

    for (int g = blockIdx.x * NW + warp; g < NGROUP; g += gridDim.x * NW) {
        const int row0 = g * ROWS;
        float xr[ROWS][4];
        float di[ROWS];
#pragma unroll
        for (int r = 0; r < ROWS; r++) {
            const int row = row0 + r;
            di[r] = g_dinv[row];
            float4 v = ((const float4*)(X + (size_t)row * D))[lane];
            xr[r][0] = v.x; xr[r][1] = v.y; xr[r][2] = v.z; xr[r][3] = v.w;
        }

        ull acc0[ROWS], acc1[ROWS];
#pragma unroll
        for (int r = 0; r < ROWS; r++) { acc0[r] = 0ull; acc1[r] = 0ull; }

#pragma unroll 4
        for (int k = 0; k < D; k++) {
            ulonglong2 w = ((const ulonglong2*)Ws)[k * 32 + lane];
#pragma unroll
            for (int r = 0; r < ROWS; r++) {
                float xv = __shfl_sync(0xffffffffu, xr[r][k & 3], k >> 2);
                ull xvv = pack2(xv, xv);
                acc0[r] = ffma2(xvv, w.x, acc0[r]);
                acc1[r] = ffma2(xvv, w.y, acc1[r]);
            }
        }

#pragma unroll
        for (int r = 0; r < ROWS; r++) {
            const int row = row0 + r;
            float2 lo = unpack2(acc0[r]);
            float2 hi = unpack2(acc1[r]);
            __half2 ha = __floats2half2_rn(lo.x * di[r], lo.y * di[r]);
            __half2 hb = __floats2half2_rn(hi.x * di[r], hi.y * di[r]);
            uint2 st;
            st.x = *(unsigned*)&ha;
            st.y = *(unsigned*)&hb;
            *(uint2*)(g_bufAh + (size_t)row * D + 4 * lane) = st;
        }
    }
}

// ---------------- CSR gather (128-dim fp16): warp per node ----------------
__global__ __launch_bounds__(256)
void k_gather()
{
    const int v = (blockIdx.x * blockDim.x + threadIdx.x) >> 5;
    if (v >= NN) return;
    const int lane = threadIdx.x & 31;
    const int start = g_rowptr[v];
    const int deg   = g_cnt[v];

    float4 acc = ldh4(g_bufAh + (size_t)v * D + 4 * lane);   // self loop

    int j = 0;
    for (; j + 4 <= deg; j += 4) {
        int s0 = __ldg(g_srcs + start + j + 0);
        int s1 = __ldg(g_srcs + start + j + 1);
        int s2 = __ldg(g_srcs + start + j + 2);
        int s3 = __ldg(g_srcs + start + j + 3);
        float4 v0 = ldh4(g_bufAh + (size_t)s0 * D + 4 * lane);
        float4 v1 = ldh4(g_bufAh + (size_t)s1 * D + 4 * lane);
        float4 v2 = ldh4(g_bufAh + (size_t)s2 * D + 4 * lane);
        float4 v3 = ldh4(g_bufAh + (size_t)s3 * D + 4 * lane);
        acc.x += v0.x + v1.x + v2.x + v3.x;
        acc.y += v0.y + v1.y + v2.y + v3.y;
        acc.z += v0.z + v1.z + v2.z + v3.z;
        acc.w += v0.w + v1.w + v2.w + v3.w;
    }
    for (; j < deg; j++) {
        int s = __ldg(g_srcs + start + j);
        float4 u = ldh4(g_bufAh + (size_t)s * D + 4 * lane);
        acc.x += u.x; acc.y += u.y; acc.z += u.z; acc.w += u.w;
    }
    ((float4*)(g_bufB + (size_t)v * D))[lane] = acc;
}

// ---------------- small GEMM: u = [relu(dinv*agg1+b1) @ W2'] * dinv -> bufUh ----------------
__global__ __launch_bounds__(256)
void k_small(const float* __restrict__ b1)
{
    extern __shared__ float Ws[];          // D*DOUT floats
    const int tid = threadIdx.x;
    for (int i = tid; i < D * DOUT; i += blockDim.x)
        Ws[i] = g_W2p[i];
    __syncthreads();

    const int lane = tid & 31, warp = tid >> 5;
    const int NW = blockDim.x >> 5;
    const bool act = (lane < DOUT / 2);

    float4 b1r = ((const float4*)b1)[lane];

    for (int g = blockIdx.x * NW + warp; g < NGROUP; g += gridDim.x * NW) {
        const int row0 = g * ROWS;
        float xr[ROWS][4];
        float di[ROWS];
#pragma unroll
        for (int r = 0; r < ROWS; r++) {
            const int row = row0 + r;
            di[r] = g_dinv[row];
            float4 a = ((const float4*)(g_bufB + (size_t)row * D))[lane];
            xr[r][0] = fmaxf(fmaf(di[r], a.x, b1r.x), 0.f);
            xr[r][1] = fmaxf(fmaf(di[r], a.y, b1r.y), 0.f);
            xr[r][2] = fmaxf(fmaf(di[r], a.z, b1r.z), 0.f);
            xr[r][3] = fmaxf(fmaf(di[r], a.w, b1r.w), 0.f);
        }

        ull acc[ROWS];
#pragma unroll
        for (int r = 0; r < ROWS; r++) acc[r] = 0ull;

#pragma unroll 4
        for (int k = 0; k < D; k++) {
            ull w = 0ull;
            if (act) w = *(const ull*)(Ws + k * DOUT + 2 * lane);
#pragma unroll
            for (int r = 0; r < ROWS; r++) {
                float xv = __shfl_sync(0xffffffffu, xr[r][k & 3], k >> 2);
                ull xvv = pack2(xv, xv);
                acc[r] = ffma2(xvv, w, acc[r]);
            }
        }

        if (act) {
#pragma unroll
            for (int r = 0; r < ROWS; r++) {
                float2 v = unpack2(acc[r]);
                __half2 h = __floats2half2_rn(v.x * di[r], v.y * di[r]);
                *(__half2*)(g_bufUh + (size_t)(row0 + r) * DOUT + 2 * lane) = h;
            }
        }
    }
}

// ---------------- CSR gather (40-dim fp16) + final epilogue: out = dinv*acc + c ----------------
__global__ __launch_bounds__(256)
void k_gather2(float* __restrict__ out)
{
    const int v = (blockIdx.x * blockDim.x + threadIdx.x) >> 5;
    if (v >= NN) return;
    const int lane = threadIdx.x & 31;
    if (lane >= DOUT / 2) return;
    const int start = g_rowptr[v];
    const int deg   = g_cnt[v];
    const float di  = g_dinv[v];

    float2 acc = __half22float2(
        *(const __half2*)(g_bufUh + (size_t)v * DOUT + 2 * lane));   // self

    int j = 0;
    for (; j + 4 <= deg; j += 4) {
        int s0 = __ldg(g_srcs + start + j + 0);
        int s1 = __ldg(g_srcs + start + j + 1);
        int s2 = __ldg(g_srcs + start + j + 2);
        int s3 = __ldg(g_srcs + start + j + 3);
        float2 v0 = __half22float2(*(const __half2*)(g_bufUh + (size_t)s0 * DOUT + 2 * lane));
        float2 v1 = __half22float2(*(const __half2*)(g_bufUh + (size_t)s1 * DOUT + 2 * lane));
        float2 v2 = __half22float2(*(const __half2*)(g_bufUh + (size_t)s2 * DOUT + 2 * lane));
        float2 v3 = __half22float2(*(const __half2*)(g_bufUh + (size_t)s3 * DOUT + 2 * lane));
        acc.x += v0.x + v1.x + v2.x + v3.x;
        acc.y += v0.y + v1.y + v2.y + v3.y;
    }
    for (; j < deg; j++) {
        int s = __ldg(g_srcs + start + j);
        float2 u = __half22float2(*(const __half2*)(g_bufUh + (size_t)s * DOUT + 2 * lane));
        acc.x += u.x; acc.y += u.y;
    }
    float2 c = *(const float2*)(g_c + 2 * lane);
    float2 o = make_float2(fmaf(di, acc.x, c.x), fmaf(di, acc.y, c.y));
    *(float2*)(out + (size_t)v * DOUT + 2 * lane) = o;
}

extern "C" void kernel_launch(void* const* d_in, const int* in_sizes, int n_in,
                              void* d_out, int out_size)
{
    const float* x    = (const float*)d_in[0];
    const int*   ei   = (const int*)  d_in[1];
    const float* W1   = (const float*)d_in[2];
    const float* b1   = (const float*)d_in[3];
    const float* W2   = (const float*)d_in[4];
    const float* b2   = (const float*)d_in[5];
    const float* Wout = (const float*)d_in[6];
    const float* bout = (const float*)d_in[7];
    const int* src = ei;
    const int* dst = ei + NE;
    float* out = (float*)d_out;

    const int SMEM_GEMM  = D * D * 4;       // 64 KB
    const int SMEM_SMALL = D * DOUT * 4;    // 20 KB

    cudaFuncSetAttribute(k_gemm, cudaFuncAttributeMaxDynamicSharedMemorySize, SMEM_GEMM);

    const int GEMM_GRID   = (NGROUP + 7) / 8;
    const int GATHER_GRID = (NN * 32 + 255) / 256;

    // ---- CSR build + weight folding ----
    k_zero<<<(NN + 255) / 256, 256>>>();
    k_hist<<<(NE + 255) / 256, 256>>>(dst);
    k_fold<<<(D * DOUT + DOUT + 255) / 256, 256>>>(W2, Wout, b2, bout);
    k_scan1<<<NSCANB, SCAN_B>>>();
    k_scan2<<<1, 256>>>();
    k_finalize<<<(NN + 255) / 256, 256>>>();
    k_scatter<<<(NE + 255) / 256, 256>>>(src, dst);

    // ---- layer 1 ----
    k_gemm<<<GEMM_GRID, 256, SMEM_GEMM>>>(x, W1);
    k_gather<<<GATHER_GRID, 256>>>();

    // ---- layer 2 folded with output layer ----
    k_small<<<GEMM_GRID, 256, SMEM_SMALL>>>(b1);
    k_gather2<<<GATHER_GRID, 256>>>(out);
}